// round 12
// baseline (speedup 1.0000x reference)
#include <cuda_runtime.h>
#include <math.h>

#define B  8
#define C  48
#define HH 192
#define WW 192
#define NN (HH*WW)   // 36864

// ---------------- scratch (no allocations allowed) ----------------
__device__ float  g_G[4*B*C*C];        // Gram matrices  [s][b][c][d]
__device__ float  g_Pt[B*4*C*C];       // P transposed   [b][s][e][co]
__device__ float  g_y1[B*C*NN];        // fuse output; overwritten with t by k_pre
__device__ float  g_U[48*48*16];       // Winograd weights [ci][co][16]
__device__ double g_stats[4*C];        // sum1, sq1, sum2, sq2
__device__ float  g_bn[4*C];           // scale1, shift1, scale2, shift2

// ---------------- zero scratch ----------------
__global__ void k_zero() {
    int i = blockIdx.x * 256 + threadIdx.x;
    if (i < 4*B*C*C) g_G[i] = 0.f;
    if (i < 4*C)     g_stats[i] = 0.0;
}

// ---------------- Winograd weight transform: U = G g G^T ----------------
__global__ void k_wtrans(const float* __restrict__ out_w) {
    const int idx = blockIdx.x * 256 + threadIdx.x;
    if (idx >= 2304) return;
    const int co = idx / 48, ci = idx - co*48;
    const float* g = out_w + (co*48 + ci)*9;
    float r[4][3];
    #pragma unroll
    for (int c = 0; c < 3; c++) {
        const float g0 = g[c], g1 = g[3+c], g2 = g[6+c];
        r[0][c] = g0;
        r[1][c] = 0.5f*(g0 + g1 + g2);
        r[2][c] = 0.5f*(g0 - g1 + g2);
        r[3][c] = g2;
    }
    float* U = g_U + (ci*48 + co)*16;
    #pragma unroll
    for (int rr = 0; rr < 4; rr++) {
        const float c0 = r[rr][0], c1 = r[rr][1], c2 = r[rr][2];
        U[rr*4+0] = c0;
        U[rr*4+1] = 0.5f*(c0 + c1 + c2);
        U[rr*4+2] = 0.5f*(c0 - c1 + c2);
        U[rr*4+3] = c2;
    }
}

// ---------------- pass A: Gram matrices — single-wave grid + register prefetch ----------------
__global__ __launch_bounds__(256) void k_gram(const float* __restrict__ xa,
                                              const float* __restrict__ xb,
                                              const float* __restrict__ xc,
                                              const float* __restrict__ xd) {
    __shared__ float sX[4][32][49];   // [tensor][n][c padded] = 25088 B
    const int b     = blockIdx.y;
    const int chunk = blockIdx.x;     // 36 chunks of 1024 n
    const int tid = threadIdx.x;
    const int tx = tid & 15, ty = tid >> 4;

    float acc[4][3][3];
    #pragma unroll
    for (int s = 0; s < 4; s++)
        #pragma unroll
        for (int i = 0; i < 3; i++)
            #pragma unroll
            for (int j = 0; j < 3; j++) acc[s][i][j] = 0.f;

    const size_t base = (size_t)b * C * NN + (size_t)chunk * 1024;
    const float* src[4] = {xa, xb, xc, xd};

    float r[24];
    #pragma unroll
    for (int k = 0; k < 24; k++) {
        const int idx = tid + 256*k;
        const int s = idx / 1536, rem = idx - s*1536;
        const int c = rem >> 5, nl = rem & 31;
        r[k] = src[s][base + (size_t)c * NN + nl];      // tile 0
    }

    for (int tile = 0; tile < 32; tile++) {
        __syncthreads();   // consumers of previous tile done
        #pragma unroll
        for (int k = 0; k < 24; k++) {
            const int idx = tid + 256*k;
            const int s = idx / 1536, rem = idx - s*1536;
            const int c = rem >> 5, nl = rem & 31;
            sX[s][nl][c] = r[k];
        }
        __syncthreads();   // smem ready
        if (tile < 31) {
            const int n0 = (tile + 1) * 32;
            #pragma unroll
            for (int k = 0; k < 24; k++) {
                const int idx = tid + 256*k;
                const int s = idx / 1536, rem = idx - s*1536;
                const int c = rem >> 5, nl = rem & 31;
                r[k] = src[s][base + (size_t)c * NN + n0 + nl];
            }
        }
        for (int n = 0; n < 32; n++) {
            const float a0 = sX[0][n][ty], a1 = sX[0][n][ty+16], a2 = sX[0][n][ty+32];
            #pragma unroll
            for (int s = 0; s < 4; s++) {
                const float b0 = sX[s][n][tx], b1 = sX[s][n][tx+16], b2 = sX[s][n][tx+32];
                acc[s][0][0] += a0*b0; acc[s][0][1] += a0*b1; acc[s][0][2] += a0*b2;
                acc[s][1][0] += a1*b0; acc[s][1][1] += a1*b1; acc[s][1][2] += a1*b2;
                acc[s][2][0] += a2*b0; acc[s][2][1] += a2*b1; acc[s][2][2] += a2*b2;
            }
        }
    }
    #pragma unroll
    for (int s = 0; s < 4; s++)
        #pragma unroll
        for (int i = 0; i < 3; i++)
            #pragma unroll
            for (int j = 0; j < 3; j++) {
                const int c = ty + 16*i, d = tx + 16*j;
                atomicAdd(&g_G[((s*B + b)*C + c)*C + d], acc[s][i][j]);
            }
}

// ---------------- pass B: energy -> attention -> M -> P (tiny) ----------------
__global__ __launch_bounds__(256) void k_attn(const float* __restrict__ Wa,
                                              const float* __restrict__ Wb,
                                              const float* __restrict__ Wc,
                                              const float* __restrict__ Wd,
                                              const float* __restrict__ fuse_w) {
    __shared__ float sA[2304];
    __shared__ float sB[2304];
    __shared__ float sC[2304];
    __shared__ float sD[2304];
    const int s = blockIdx.x, b = blockIdx.y, tid = threadIdx.x;
    const float* Wsp = (s == 0) ? Wa : (s == 1) ? Wb : (s == 2) ? Wc : Wd;

    for (int i = tid; i < 2304; i += 256) {
        sA[i] = g_G[(s*B + b)*2304 + i];
        sB[i] = Wa[i];
        sC[i] = Wsp[i];
    }
    __syncthreads();
    for (int i = tid; i < 2304; i += 256) {
        const int e = i / 48, d = i % 48;
        float a = 0.f;
        for (int f = 0; f < 48; f++) a += sA[e*48+f] * sC[d*48+f];
        sD[i] = a;
    }
    __syncthreads();
    for (int i = tid; i < 2304; i += 256) {
        const int c = i / 48, d = i % 48;
        float a = 0.f;
        for (int e = 0; e < 48; e++) a += sB[c*48+e] * sD[e*48+d];
        sA[i] = a;
    }
    __syncthreads();
    if (tid < 48) {
        const int c = tid;
        float mn = sA[c*48];
        for (int d = 1; d < 48; d++) mn = fminf(mn, sA[c*48+d]);
        float sum = 0.f;
        for (int d = 0; d < 48; d++) { const float v = expf(mn - sA[c*48+d]); sD[c*48+d] = v; sum += v; }
        const float inv = 1.f / sum;
        for (int d = 0; d < 48; d++) sD[c*48+d] *= inv;
    }
    for (int i = tid; i < 2304; i += 256) {
        const int co = i / 48, c = i % 48;
        sB[i] = fuse_w[co*192 + s*48 + c];
    }
    __syncthreads();
    for (int i = tid; i < 2304; i += 256) {
        const int co = i / 48, d = i % 48;
        float a = 0.f;
        for (int c = 0; c < 48; c++) a += sB[co*48+c] * sD[c*48+d];
        sA[i] = a;
    }
    __syncthreads();
    for (int i = tid; i < 2304; i += 256) {
        const int co = i / 48, e = i % 48;
        float a = 0.f;
        for (int d = 0; d < 48; d++) a += sA[co*48+d] * sC[d*48+e];
        g_Pt[(((size_t)b*4 + s)*48 + e)*48 + co] = a;
    }
}

// ---------------- pass C: fused 1x1 conv with register double-buffered staging ----------------
__global__ __launch_bounds__(256) void k_fuse(const float* __restrict__ xa,
                                              const float* __restrict__ xb,
                                              const float* __restrict__ xc,
                                              const float* __restrict__ xd,
                                              const float* __restrict__ fuse_b) {
    __shared__ float sW[48][48];     // [e][co]  9216 B
    __shared__ float sX[24][256];    // [e][n]  24576 B
    __shared__ float sstats[96];
    const int b  = blockIdx.y;
    const int n0 = blockIdx.x * 256;
    const int tid = threadIdx.x, tx = tid & 31, ty = tid >> 5;

    if (tid < 96) sstats[tid] = 0.f;

    float acc[6][8];
    #pragma unroll
    for (int i = 0; i < 6; i++)
        #pragma unroll
        for (int j = 0; j < 8; j++) acc[i][j] = 0.f;

    const float* src[4] = {xa, xb, xc, xd};
    const size_t xbase = (size_t)b*48*NN + n0 + tid;   // + e*NN
    const float* ptb = &g_Pt[(size_t)b*4*2304];        // + s*2304

    float xr[24];
    #pragma unroll
    for (int k = 0; k < 24; k++) xr[k] = src[0][xbase + (size_t)k*NN];
    float wr[9];
    #pragma unroll
    for (int j = 0; j < 9; j++) wr[j] = ptb[tid + 256*j];

    for (int step = 0; step < 8; step++) {
        const int ch = step & 1, e0 = ch * 24;
        __syncthreads();   // previous compute done
        if (ch == 0) {
            #pragma unroll
            for (int j = 0; j < 9; j++) sW[0][tid + 256*j] = wr[j];
        }
        #pragma unroll
        for (int k = 0; k < 24; k++) sX[k][tid] = xr[k];
        __syncthreads();   // smem ready
        if (step < 7) {
            const int ns = (step + 1) >> 1, nch = (step + 1) & 1, ne0 = nch * 24;
            const float* nf = src[ns];
            #pragma unroll
            for (int k = 0; k < 24; k++) xr[k] = nf[xbase + (size_t)(ne0 + k)*NN];
            if (nch == 0) {
                #pragma unroll
                for (int j = 0; j < 9; j++) wr[j] = ptb[ns*2304 + tid + 256*j];
            }
        }
        #pragma unroll 2
        for (int el = 0; el < 24; el++) {
            const float4 x0 = *(const float4*)&sX[el][4*tx];
            const float4 x1 = *(const float4*)&sX[el][4*tx + 128];
            #pragma unroll
            for (int i = 0; i < 6; i++) {
                const float wv = sW[e0 + el][ty + 8*i];
                acc[i][0] += wv*x0.x; acc[i][1] += wv*x0.y;
                acc[i][2] += wv*x0.z; acc[i][3] += wv*x0.w;
                acc[i][4] += wv*x1.x; acc[i][5] += wv*x1.y;
                acc[i][6] += wv*x1.z; acc[i][7] += wv*x1.w;
            }
        }
    }
    __syncthreads();

    #pragma unroll
    for (int i = 0; i < 6; i++) {
        const int co = ty + 8*i;           // warp-uniform
        const float fb_ = fuse_b[co];
        float4 o0, o1;
        o0.x = acc[i][0]+fb_; o0.y = acc[i][1]+fb_; o0.z = acc[i][2]+fb_; o0.w = acc[i][3]+fb_;
        o1.x = acc[i][4]+fb_; o1.y = acc[i][5]+fb_; o1.z = acc[i][6]+fb_; o1.w = acc[i][7]+fb_;
        float* row = &g_y1[((size_t)b*48 + co)*NN + n0];
        *(float4*)&row[4*tx]       = o0;
        *(float4*)&row[4*tx + 128] = o1;
        float lsum = o0.x+o0.y+o0.z+o0.w + o1.x+o1.y+o1.z+o1.w;
        float lsq  = o0.x*o0.x+o0.y*o0.y+o0.z*o0.z+o0.w*o0.w
                   + o1.x*o1.x+o1.y*o1.y+o1.z*o1.z+o1.w*o1.w;
        for (int o = 16; o > 0; o >>= 1) {
            lsum += __shfl_down_sync(0xffffffffu, lsum, o);
            lsq  += __shfl_down_sync(0xffffffffu, lsq,  o);
        }
        if (tx == 0) { atomicAdd(&sstats[co], lsum); atomicAdd(&sstats[48+co], lsq); }
    }
    __syncthreads();
    if (tid < 48) {
        atomicAdd(&g_stats[tid],      (double)sstats[tid]);
        atomicAdd(&g_stats[48 + tid], (double)sstats[48 + tid]);
    }
}

// ---------------- BN finalize (tiny) ----------------
__global__ void k_bnfin(const float* __restrict__ gamma, const float* __restrict__ beta, int which) {
    const int c = threadIdx.x;
    if (c >= 48) return;
    const double cnt  = (double)B * NN;
    const double mean = g_stats[which*96 + c] / cnt;
    const double var  = g_stats[which*96 + 48 + c] / cnt - mean*mean;
    const float  sc   = (float)((double)gamma[c] / sqrt(var + 1e-5));
    const float  sh   = beta[c] - (float)mean * sc;
    g_bn[which*96 + c]      = sc;
    g_bn[which*96 + 48 + c] = sh;
}

// ---------------- pass D: t = gamma_cam*relu(bn1(y1)) + input, in place into g_y1 ----------------
__global__ void k_pre(const float* __restrict__ inp, const float* __restrict__ gamma_cam) {
    const size_t i = ((size_t)blockIdx.x * 256 + threadIdx.x) * 4;
    const int co = (int)((i / NN) % 48);
    const float sc = g_bn[co], sh = g_bn[48 + co];
    const float gcam = gamma_cam[0];
    float4 y = *(float4*)(g_y1 + i);
    const float4 x = *(const float4*)(inp + i);
    y.x = gcam * fmaxf(y.x*sc + sh, 0.f) + x.x;
    y.y = gcam * fmaxf(y.y*sc + sh, 0.f) + x.y;
    y.z = gcam * fmaxf(y.z*sc + sh, 0.f) + x.z;
    y.w = gcam * fmaxf(y.w*sc + sh, 0.f) + x.w;
    *(float4*)(g_y1 + i) = y;
}

// ---------------- pass E: 3x3 conv via Winograd F(2x2,3x3), reg double-buffered staging ----------------
// block: 384 threads = 12 warps; warp w owns co = 4w..4w+3; lane = 2x2 tile (4 rows x 8 cols)
// region per block: 8 rows x 16 cols of output; grid (12, 24, B)
__global__ __launch_bounds__(384) void k_conv(const float* __restrict__ out_b,
                                              float* __restrict__ out) {
    __shared__ float sT[180];        // 10 x 18 padded input tile
    __shared__ float sU[768];        // 48 co x 16 transformed weights (current ci)
    __shared__ float ssum[48], ssq[48];
    const int b   = blockIdx.z;
    const int hy0 = blockIdx.y * 8;
    const int wx0 = blockIdx.x * 16;
    const int tid = threadIdx.x;
    const int wid = tid >> 5, lane = tid & 31;
    const int tr = lane >> 3, tc = lane & 7;
    const int cobase = wid * 4;

    if (tid < 48) { ssum[tid] = 0.f; ssq[tid] = 0.f; }

    // staging decode (hoisted)
    const int rr0 = tid / 18, cc0 = tid - rr0*18;
    const int gh0 = hy0 + rr0 - 1, gw0 = wx0 + cc0 - 1;
    const bool tok = (tid < 180) && (gh0 >= 0 && gh0 < HH && gw0 >= 0 && gw0 < WW);
    const int toff = tok ? (gh0*WW + gw0) : 0;
    const float* tbase = g_y1 + (size_t)b*48*NN;

    // prefetch ci = 0
    float tin = tok ? tbase[toff] : 0.f;
    float wa = g_U[tid];
    float wb = g_U[tid + 384];

    float M[4][16];
    #pragma unroll
    for (int j = 0; j < 4; j++)
        #pragma unroll
        for (int k = 0; k < 16; k++) M[j][k] = 0.f;

    for (int ci = 0; ci < 48; ci++) {
        __syncthreads();   // previous compute done
        if (tid < 180) sT[tid] = tin;
        sU[tid] = wa; sU[tid + 384] = wb;
        __syncthreads();   // smem ready
        if (ci < 47) {
            tin = tok ? tbase[(size_t)(ci + 1)*NN + toff] : 0.f;
            wa = g_U[(ci + 1)*768 + tid];
            wb = g_U[(ci + 1)*768 + tid + 384];
        }

        // load 4x4 patch
        float d[16];
        #pragma unroll
        for (int rr = 0; rr < 4; rr++) {
            const float2 p0 = *(const float2*)&sT[(2*tr + rr)*18 + 2*tc];
            const float2 p1 = *(const float2*)&sT[(2*tr + rr)*18 + 2*tc + 2];
            d[rr*4+0] = p0.x; d[rr*4+1] = p0.y; d[rr*4+2] = p1.x; d[rr*4+3] = p1.y;
        }
        // V = B^T d B, in place
        #pragma unroll
        for (int c = 0; c < 4; c++) {
            const float t0 = d[c]     - d[8+c];
            const float t1 = d[4+c]   + d[8+c];
            const float t2 = d[8+c]   - d[4+c];
            const float t3 = d[4+c]   - d[12+c];
            d[c] = t0; d[4+c] = t1; d[8+c] = t2; d[12+c] = t3;
        }
        #pragma unroll
        for (int r = 0; r < 4; r++) {
            const float t0 = d[r*4+0] - d[r*4+2];
            const float t1 = d[r*4+1] + d[r*4+2];
            const float t2 = d[r*4+2] - d[r*4+1];
            const float t3 = d[r*4+1] - d[r*4+3];
            d[r*4+0] = t0; d[r*4+1] = t1; d[r*4+2] = t2; d[r*4+3] = t3;
        }
        // M[j] += U(co) ∘ V   (warp-uniform co -> broadcast loads)
        #pragma unroll
        for (int j = 0; j < 4; j++) {
            const float4* Up = (const float4*)&sU[(cobase + j)*16];
            const float4 u0 = Up[0], u1 = Up[1], u2 = Up[2], u3 = Up[3];
            M[j][0]  += u0.x*d[0];  M[j][1]  += u0.y*d[1];  M[j][2]  += u0.z*d[2];  M[j][3]  += u0.w*d[3];
            M[j][4]  += u1.x*d[4];  M[j][5]  += u1.y*d[5];  M[j][6]  += u1.z*d[6];  M[j][7]  += u1.w*d[7];
            M[j][8]  += u2.x*d[8];  M[j][9]  += u2.y*d[9];  M[j][10] += u2.z*d[10]; M[j][11] += u2.w*d[11];
            M[j][12] += u3.x*d[12]; M[j][13] += u3.y*d[13]; M[j][14] += u3.z*d[14]; M[j][15] += u3.w*d[15];
        }
    }

    // epilogue: Y = A^T M A per co, + bias, store, BN2 stats
    #pragma unroll
    for (int j = 0; j < 4; j++) {
        const int co = cobase + j;
        const float bo = out_b[co];
        float t0[4], t1[4];
        #pragma unroll
        for (int c = 0; c < 4; c++) {
            t0[c] = M[j][c] + M[j][4+c] + M[j][8+c];
            t1[c] = M[j][4+c] - M[j][8+c] - M[j][12+c];
        }
        const float v00 = t0[0] + t0[1] + t0[2] + bo;
        const float v01 = t0[1] - t0[2] - t0[3] + bo;
        const float v10 = t1[0] + t1[1] + t1[2] + bo;
        const float v11 = t1[1] - t1[2] - t1[3] + bo;
        const int gh = hy0 + 2*tr, gw = wx0 + 2*tc;
        float* rowp = out + ((size_t)b*48 + co)*NN + gh*WW + gw;
        *(float2*)rowp        = make_float2(v00, v01);
        *(float2*)(rowp + WW) = make_float2(v10, v11);
        float lsum = v00 + v01 + v10 + v11;
        float lsq  = v00*v00 + v01*v01 + v10*v10 + v11*v11;
        #pragma unroll
        for (int o = 16; o > 0; o >>= 1) {
            lsum += __shfl_down_sync(0xffffffffu, lsum, o);
            lsq  += __shfl_down_sync(0xffffffffu, lsq,  o);
        }
        if (lane == 0) { atomicAdd(&ssum[co], lsum); atomicAdd(&ssq[co], lsq); }
    }
    __syncthreads();
    if (tid < 48) {
        atomicAdd(&g_stats[96 + tid],  (double)ssum[tid]);
        atomicAdd(&g_stats[144 + tid], (double)ssq[tid]);
    }
}

// ---------------- pass G: in-place relu(bn2(y2)) ----------------
__global__ void k_final(float* __restrict__ out) {
    const size_t i = ((size_t)blockIdx.x * 256 + threadIdx.x) * 4;
    const int co = (int)((i / NN) % 48);
    const float sc = g_bn[96 + co], sh = g_bn[144 + co];
    float4 v = *(float4*)(out + i);
    v.x = fmaxf(v.x*sc + sh, 0.f);
    v.y = fmaxf(v.y*sc + sh, 0.f);
    v.z = fmaxf(v.z*sc + sh, 0.f);
    v.w = fmaxf(v.w*sc + sh, 0.f);
    *(float4*)(out + i) = v;
}

// ---------------- launch ----------------
extern "C" void kernel_launch(void* const* d_in, const int* in_sizes, int n_in,
                              void* d_out, int out_size) {
    const float* xa         = (const float*)d_in[0];
    const float* fb         = (const float*)d_in[1];
    const float* fc         = (const float*)d_in[2];
    const float* fd         = (const float*)d_in[3];
    const float* Wa         = (const float*)d_in[4];
    const float* Wb         = (const float*)d_in[5];
    const float* Wc         = (const float*)d_in[6];
    const float* Wd         = (const float*)d_in[7];
    const float* fuse_w     = (const float*)d_in[8];
    const float* fuse_b     = (const float*)d_in[9];
    const float* fuse_gamma = (const float*)d_in[10];
    const float* fuse_beta  = (const float*)d_in[11];
    const float* gamma_cam  = (const float*)d_in[12];
    const float* out_w      = (const float*)d_in[13];
    const float* out_b      = (const float*)d_in[14];
    const float* out_gamma  = (const float*)d_in[15];
    const float* out_beta   = (const float*)d_in[16];
    float* out = (float*)d_out;

    k_zero<<<288, 256>>>();
    k_wtrans<<<9, 256>>>(out_w);
    k_gram<<<dim3(36, B), 256>>>(xa, fb, fc, fd);
    k_attn<<<dim3(4, B), 256>>>(Wa, Wb, Wc, Wd, fuse_w);
    k_fuse<<<dim3(NN/256, B), 256>>>(xa, fb, fc, fd, fuse_b);
    k_bnfin<<<1, 48>>>(fuse_gamma, fuse_beta, 0);
    k_pre<<<(B*C*NN)/1024, 256>>>(xa, gamma_cam);
    k_conv<<<dim3(12, 24, B), 384>>>(out_b, out);
    k_bnfin<<<1, 48>>>(out_gamma, out_beta, 1);
    k_final<<<(B*C*NN)/1024, 256>>>(out);
}

// round 13
// speedup vs baseline: 1.7162x; 1.7162x over previous
#include <cuda_runtime.h>
#include <math.h>

#define B  8
#define C  48
#define HH 192
#define WW 192
#define NN (HH*WW)   // 36864

// ---------------- scratch (no allocations allowed) ----------------
__device__ float  g_G[4*B*C*C];        // Gram matrices  [s][b][c][d]
__device__ float  g_Pt[B*4*C*C];       // P transposed   [b][s][e][co]
__device__ float  g_y1[B*C*NN];        // fuse output; overwritten with t by k_pre
__device__ double g_stats[4*C];        // sum1, sq1, sum2, sq2
__device__ float  g_bn[4*C];           // scale1, shift1, scale2, shift2

__device__ __forceinline__ float dot48(const float* __restrict__ a, const float* __restrict__ b) {
    float s = 0.f;
    #pragma unroll
    for (int k = 0; k < 12; k++) {
        const float4 x = ((const float4*)a)[k];
        const float4 y = ((const float4*)b)[k];
        s += x.x*y.x + x.y*y.y + x.z*y.z + x.w*y.w;
    }
    return s;
}

// ---------------- zero scratch ----------------
__global__ void k_zero() {
    int i = blockIdx.x * 256 + threadIdx.x;
    if (i < 4*B*C*C) g_G[i] = 0.f;
    if (i < 4*C)     g_stats[i] = 0.0;
}

// ---------------- pass A: Gram matrices — single-wave grid + register prefetch ----------------
__global__ __launch_bounds__(256) void k_gram(const float* __restrict__ xa,
                                              const float* __restrict__ xb,
                                              const float* __restrict__ xc,
                                              const float* __restrict__ xd) {
    __shared__ float sX[4][32][49];   // [tensor][n][c padded] = 25088 B
    const int b     = blockIdx.y;
    const int chunk = blockIdx.x;     // 36 chunks of 1024 n
    const int tid = threadIdx.x;
    const int tx = tid & 15, ty = tid >> 4;

    float acc[4][3][3];
    #pragma unroll
    for (int s = 0; s < 4; s++)
        #pragma unroll
        for (int i = 0; i < 3; i++)
            #pragma unroll
            for (int j = 0; j < 3; j++) acc[s][i][j] = 0.f;

    const size_t base = (size_t)b * C * NN + (size_t)chunk * 1024;
    const float* src[4] = {xa, xb, xc, xd};

    float r[24];
    #pragma unroll
    for (int k = 0; k < 24; k++) {
        const int idx = tid + 256*k;
        const int s = idx / 1536, rem = idx - s*1536;
        const int c = rem >> 5, nl = rem & 31;
        r[k] = src[s][base + (size_t)c * NN + nl];      // tile 0
    }

    for (int tile = 0; tile < 32; tile++) {
        __syncthreads();   // consumers of previous tile done
        #pragma unroll
        for (int k = 0; k < 24; k++) {
            const int idx = tid + 256*k;
            const int s = idx / 1536, rem = idx - s*1536;
            const int c = rem >> 5, nl = rem & 31;
            sX[s][nl][c] = r[k];
        }
        __syncthreads();   // smem ready
        if (tile < 31) {
            const int n0 = (tile + 1) * 32;
            #pragma unroll
            for (int k = 0; k < 24; k++) {
                const int idx = tid + 256*k;
                const int s = idx / 1536, rem = idx - s*1536;
                const int c = rem >> 5, nl = rem & 31;
                r[k] = src[s][base + (size_t)c * NN + n0 + nl];
            }
        }
        for (int n = 0; n < 32; n++) {
            const float a0 = sX[0][n][ty], a1 = sX[0][n][ty+16], a2 = sX[0][n][ty+32];
            #pragma unroll
            for (int s = 0; s < 4; s++) {
                const float b0 = sX[s][n][tx], b1 = sX[s][n][tx+16], b2 = sX[s][n][tx+32];
                acc[s][0][0] += a0*b0; acc[s][0][1] += a0*b1; acc[s][0][2] += a0*b2;
                acc[s][1][0] += a1*b0; acc[s][1][1] += a1*b1; acc[s][1][2] += a1*b2;
                acc[s][2][0] += a2*b0; acc[s][2][1] += a2*b1; acc[s][2][2] += a2*b2;
            }
        }
    }
    #pragma unroll
    for (int s = 0; s < 4; s++)
        #pragma unroll
        for (int i = 0; i < 3; i++)
            #pragma unroll
            for (int j = 0; j < 3; j++) {
                const int c = ty + 16*i, d = tx + 16*j;
                atomicAdd(&g_G[((s*B + b)*C + c)*C + d], acc[s][i][j]);
            }
}

// ---------------- pass B: energy -> attention -> M -> P — float4 inner-product version ----------------
// all 48x48 matrices row-major with pad-52 rows; T and attention stored transposed so every
// GEMM stage is a stride-1 x stride-1 inner product.
__global__ __launch_bounds__(256) void k_attn(const float* __restrict__ Wa,
                                              const float* __restrict__ Wb,
                                              const float* __restrict__ Wc,
                                              const float* __restrict__ Wd,
                                              const float* __restrict__ fuse_w) {
    __shared__ float sA[48*52];   // G -> E -> M
    __shared__ float sB[48*52];   // Wa -> FW -> Ws^T
    __shared__ float sC[48*52];   // Ws
    __shared__ float sD[48*52];   // T^T -> attn^T
    const int s = blockIdx.x, b = blockIdx.y, tid = threadIdx.x;
    const float* Wsp = (s == 0) ? Wa : (s == 1) ? Wb : (s == 2) ? Wc : Wd;

    for (int i = tid; i < 2304; i += 256) {
        const int r = i / 48, q = i - r*48;
        sA[r*52+q] = g_G[(s*B + b)*2304 + i];
        sB[r*52+q] = Wa[i];
        sC[r*52+q] = Wsp[i];
    }
    __syncthreads();
    // T[e][d] = sum_f G[e][f] * Ws[d][f]  -> store transposed D[d][e]
    for (int i = tid; i < 2304; i += 256) {
        const int e = i / 48, d = i - e*48;
        sD[d*52+e] = dot48(&sA[e*52], &sC[d*52]);
    }
    __syncthreads();
    // E[c][d] = sum_e Wa[c][e] * T[e][d] = dot(B row c, D row d)  -> A[c][d]
    for (int i = tid; i < 2304; i += 256) {
        const int c = i / 48, d = i - c*48;
        sA[c*52+d] = dot48(&sB[c*52], &sD[d*52]);
    }
    __syncthreads();
    // softmax(max-E) == softmax(-E), min-subtracted; store attn transposed D[d][c]
    if (tid < 48) {
        const int c = tid;
        float mn = sA[c*52];
        for (int d = 1; d < 48; d++) mn = fminf(mn, sA[c*52+d]);
        float sum = 0.f;
        for (int d = 0; d < 48; d++) { const float v = expf(mn - sA[c*52+d]); sD[d*52+c] = v; sum += v; }
        const float inv = 1.f / sum;
        for (int d = 0; d < 48; d++) sD[d*52+c] *= inv;
    }
    // stage FW into B (Wa dead)
    for (int i = tid; i < 2304; i += 256) {
        const int co = i / 48, c = i - co*48;
        sB[co*52+c] = fuse_w[co*192 + s*48 + c];
    }
    __syncthreads();
    // M[co][d] = sum_c FW[co][c] * attn[c][d] = dot(B row co, D row d)  -> A[co][d] (E dead)
    for (int i = tid; i < 2304; i += 256) {
        const int co = i / 48, d = i - co*48;
        sA[co*52+d] = dot48(&sB[co*52], &sD[d*52]);
    }
    __syncthreads();
    // transpose Ws into B (FW dead): B[e][d] = Ws[d][e]
    for (int i = tid; i < 2304; i += 256) {
        const int d = i / 48, e = i - d*48;
        sB[e*52+d] = sC[d*52+e];
    }
    __syncthreads();
    // P[co][e] = sum_d M[co][d] * Ws[d][e] = dot(A row co, B row e)
    for (int i = tid; i < 2304; i += 256) {
        const int co = i / 48, e = i - co*48;
        g_Pt[(((size_t)b*4 + s)*48 + e)*48 + co] = dot48(&sA[co*52], &sB[e*52]);
    }
}

// ---------------- pass C: fused 1x1 conv with register double-buffered staging ----------------
__global__ __launch_bounds__(256) void k_fuse(const float* __restrict__ xa,
                                              const float* __restrict__ xb,
                                              const float* __restrict__ xc,
                                              const float* __restrict__ xd,
                                              const float* __restrict__ fuse_b) {
    __shared__ float sW[48][48];     // [e][co]  9216 B
    __shared__ float sX[24][256];    // [e][n]  24576 B
    __shared__ float sstats[96];
    const int b  = blockIdx.y;
    const int n0 = blockIdx.x * 256;
    const int tid = threadIdx.x, tx = tid & 31, ty = tid >> 5;

    if (tid < 96) sstats[tid] = 0.f;

    float acc[6][8];
    #pragma unroll
    for (int i = 0; i < 6; i++)
        #pragma unroll
        for (int j = 0; j < 8; j++) acc[i][j] = 0.f;

    const float* src[4] = {xa, xb, xc, xd};
    const size_t xbase = (size_t)b*48*NN + n0 + tid;   // + e*NN
    const float* ptb = &g_Pt[(size_t)b*4*2304];        // + s*2304

    float xr[24];
    #pragma unroll
    for (int k = 0; k < 24; k++) xr[k] = src[0][xbase + (size_t)k*NN];
    float wr[9];
    #pragma unroll
    for (int j = 0; j < 9; j++) wr[j] = ptb[tid + 256*j];

    for (int step = 0; step < 8; step++) {
        const int ch = step & 1, e0 = ch * 24;
        __syncthreads();   // previous compute done
        if (ch == 0) {
            #pragma unroll
            for (int j = 0; j < 9; j++) sW[0][tid + 256*j] = wr[j];
        }
        #pragma unroll
        for (int k = 0; k < 24; k++) sX[k][tid] = xr[k];
        __syncthreads();   // smem ready
        if (step < 7) {
            const int ns = (step + 1) >> 1, nch = (step + 1) & 1, ne0 = nch * 24;
            const float* nf = src[ns];
            #pragma unroll
            for (int k = 0; k < 24; k++) xr[k] = nf[xbase + (size_t)(ne0 + k)*NN];
            if (nch == 0) {
                #pragma unroll
                for (int j = 0; j < 9; j++) wr[j] = ptb[ns*2304 + tid + 256*j];
            }
        }
        #pragma unroll 2
        for (int el = 0; el < 24; el++) {
            const float4 x0 = *(const float4*)&sX[el][4*tx];
            const float4 x1 = *(const float4*)&sX[el][4*tx + 128];
            #pragma unroll
            for (int i = 0; i < 6; i++) {
                const float wv = sW[e0 + el][ty + 8*i];
                acc[i][0] += wv*x0.x; acc[i][1] += wv*x0.y;
                acc[i][2] += wv*x0.z; acc[i][3] += wv*x0.w;
                acc[i][4] += wv*x1.x; acc[i][5] += wv*x1.y;
                acc[i][6] += wv*x1.z; acc[i][7] += wv*x1.w;
            }
        }
    }
    __syncthreads();

    #pragma unroll
    for (int i = 0; i < 6; i++) {
        const int co = ty + 8*i;           // warp-uniform
        const float fb_ = fuse_b[co];
        float4 o0, o1;
        o0.x = acc[i][0]+fb_; o0.y = acc[i][1]+fb_; o0.z = acc[i][2]+fb_; o0.w = acc[i][3]+fb_;
        o1.x = acc[i][4]+fb_; o1.y = acc[i][5]+fb_; o1.z = acc[i][6]+fb_; o1.w = acc[i][7]+fb_;
        float* row = &g_y1[((size_t)b*48 + co)*NN + n0];
        *(float4*)&row[4*tx]       = o0;
        *(float4*)&row[4*tx + 128] = o1;
        float lsum = o0.x+o0.y+o0.z+o0.w + o1.x+o1.y+o1.z+o1.w;
        float lsq  = o0.x*o0.x+o0.y*o0.y+o0.z*o0.z+o0.w*o0.w
                   + o1.x*o1.x+o1.y*o1.y+o1.z*o1.z+o1.w*o1.w;
        for (int o = 16; o > 0; o >>= 1) {
            lsum += __shfl_down_sync(0xffffffffu, lsum, o);
            lsq  += __shfl_down_sync(0xffffffffu, lsq,  o);
        }
        if (tx == 0) { atomicAdd(&sstats[co], lsum); atomicAdd(&sstats[48+co], lsq); }
    }
    __syncthreads();
    if (tid < 48) {
        atomicAdd(&g_stats[tid],      (double)sstats[tid]);
        atomicAdd(&g_stats[48 + tid], (double)sstats[48 + tid]);
    }
}

// ---------------- BN finalize (tiny) ----------------
__global__ void k_bnfin(const float* __restrict__ gamma, const float* __restrict__ beta, int which) {
    const int c = threadIdx.x;
    if (c >= 48) return;
    const double cnt  = (double)B * NN;
    const double mean = g_stats[which*96 + c] / cnt;
    const double var  = g_stats[which*96 + 48 + c] / cnt - mean*mean;
    const float  sc   = (float)((double)gamma[c] / sqrt(var + 1e-5));
    const float  sh   = beta[c] - (float)mean * sc;
    g_bn[which*96 + c]      = sc;
    g_bn[which*96 + 48 + c] = sh;
}

// ---------------- pass D: t = gamma_cam*relu(bn1(y1)) + input, in place into g_y1 ----------------
__global__ void k_pre(const float* __restrict__ inp, const float* __restrict__ gamma_cam) {
    const size_t i = ((size_t)blockIdx.x * 256 + threadIdx.x) * 4;
    const int co = (int)((i / NN) % 48);
    const float sc = g_bn[co], sh = g_bn[48 + co];
    const float gcam = gamma_cam[0];
    float4 y = *(float4*)(g_y1 + i);
    const float4 x = *(const float4*)(inp + i);
    y.x = gcam * fmaxf(y.x*sc + sh, 0.f) + x.x;
    y.y = gcam * fmaxf(y.y*sc + sh, 0.f) + x.y;
    y.z = gcam * fmaxf(y.z*sc + sh, 0.f) + x.z;
    y.w = gcam * fmaxf(y.w*sc + sh, 0.f) + x.w;
    *(float4*)(g_y1 + i) = y;
}

// ---------------- pass E: 3x3 conv with register double-buffered staging (R11 proven) ----------------
__global__ __launch_bounds__(256) void k_conv(const float* __restrict__ out_w,
                                              const float* __restrict__ out_b,
                                              float* __restrict__ out) {
    __shared__ float sW[48*9];
    __shared__ float sT[10*34];
    __shared__ float ssum[48], ssq[48];
    const int b   = blockIdx.z;
    const int hy0 = blockIdx.y * 8;
    const int wx0 = blockIdx.x * 32;
    const int tid = threadIdx.x;
    const int cg  = tid >> 6;
    const int p   = tid & 63;
    const int px  = p & 31;
    const int py2 = p >> 5;

    if (tid < 48) { ssum[tid] = 0.f; ssq[tid] = 0.f; }

    const int r0 = tid / 34, c0 = tid - r0*34;
    const int gh0 = hy0 + r0 - 1, gw0 = wx0 + c0 - 1;
    const bool ok0 = (gh0 >= 0 && gh0 < HH && gw0 >= 0 && gw0 < WW) && (tid < 340);
    const int off0 = ok0 ? (gh0*WW + gw0) : 0;
    const int i1 = tid + 256;
    const int r1 = i1 / 34, c1 = i1 - r1*34;
    const int gh1 = hy0 + r1 - 1, gw1 = wx0 + c1 - 1;
    const bool ok1 = (i1 < 340) && (gh1 >= 0 && gh1 < HH && gw1 >= 0 && gw1 < WW);
    const int off1 = ok1 ? (gh1*WW + gw1) : 0;
    const bool st1 = (i1 < 340);
    const int wco0 = tid / 9, wk0 = tid - wco0*9;
    const int wbase0 = wco0*432 + wk0;
    const int wco1 = i1 / 9, wk1 = i1 - wco1*9;
    const int wbase1 = wco1*432 + wk1;
    const bool wok1 = (i1 < 432);

    const float* tbase = g_y1 + (size_t)b*48*NN;

    float t0 = ok0 ? tbase[off0] : 0.f;
    float t1 = ok1 ? tbase[off1] : 0.f;
    float w0 = out_w[wbase0];
    float w1 = wok1 ? out_w[wbase1] : 0.f;

    float acc[48];
    #pragma unroll
    for (int i = 0; i < 48; i++) acc[i] = 0.f;

    for (int ci = 0; ci < 48; ci++) {
        __syncthreads();   // previous compute done
        if (tid < 340) sT[tid] = t0;
        if (st1)       sT[i1]  = t1;
        sW[tid] = w0;
        if (wok1) sW[i1] = w1;
        __syncthreads();   // smem ready
        if (ci < 47) {
            const float* tp = tbase + (size_t)(ci + 1)*NN;
            t0 = ok0 ? tp[off0] : 0.f;
            t1 = ok1 ? tp[off1] : 0.f;
            w0 = out_w[wbase0 + (ci + 1)*9];
            w1 = wok1 ? out_w[wbase1 + (ci + 1)*9] : 0.f;
        }

        float v[6][3];
        const int baseRow = py2 * 4;
        #pragma unroll
        for (int rr = 0; rr < 6; rr++)
            #pragma unroll
            for (int cc = 0; cc < 3; cc++)
                v[rr][cc] = sT[(baseRow + rr)*34 + px + cc];

        #pragma unroll
        for (int j = 0; j < 12; j++) {
            const float* wp = &sW[(cg*12 + j)*9];
            const float q0=wp[0],q1=wp[1],q2=wp[2],q3=wp[3],q4=wp[4],q5=wp[5],q6=wp[6],q7=wp[7],q8=wp[8];
            #pragma unroll
            for (int r = 0; r < 4; r++) {
                acc[j*4 + r] += q0*v[r  ][0] + q1*v[r  ][1] + q2*v[r  ][2]
                              + q3*v[r+1][0] + q4*v[r+1][1] + q5*v[r+1][2]
                              + q6*v[r+2][0] + q7*v[r+2][1] + q8*v[r+2][2];
            }
        }
    }

    #pragma unroll
    for (int j = 0; j < 12; j++) {
        const int co = cg*12 + j;
        const float bo = out_b[co];
        float lsum = 0.f, lsq = 0.f;
        #pragma unroll
        for (int r = 0; r < 4; r++) {
            const float val = acc[j*4 + r] + bo;
            const int gh = hy0 + py2*4 + r, gw = wx0 + px;
            out[((size_t)b*48 + co)*NN + gh*WW + gw] = val;
            lsum += val; lsq += val*val;
        }
        for (int o = 16; o > 0; o >>= 1) {
            lsum += __shfl_down_sync(0xffffffffu, lsum, o);
            lsq  += __shfl_down_sync(0xffffffffu, lsq,  o);
        }
        if ((tid & 31) == 0) { atomicAdd(&ssum[co], lsum); atomicAdd(&ssq[co], lsq); }
    }
    __syncthreads();
    if (tid < 48) {
        atomicAdd(&g_stats[96 + tid],  (double)ssum[tid]);
        atomicAdd(&g_stats[144 + tid], (double)ssq[tid]);
    }
}

// ---------------- pass G: in-place relu(bn2(y2)) ----------------
__global__ void k_final(float* __restrict__ out) {
    const size_t i = ((size_t)blockIdx.x * 256 + threadIdx.x) * 4;
    const int co = (int)((i / NN) % 48);
    const float sc = g_bn[96 + co], sh = g_bn[144 + co];
    float4 v = *(float4*)(out + i);
    v.x = fmaxf(v.x*sc + sh, 0.f);
    v.y = fmaxf(v.y*sc + sh, 0.f);
    v.z = fmaxf(v.z*sc + sh, 0.f);
    v.w = fmaxf(v.w*sc + sh, 0.f);
    *(float4*)(out + i) = v;
}

// ---------------- launch ----------------
extern "C" void kernel_launch(void* const* d_in, const int* in_sizes, int n_in,
                              void* d_out, int out_size) {
    const float* xa         = (const float*)d_in[0];
    const float* fb         = (const float*)d_in[1];
    const float* fc         = (const float*)d_in[2];
    const float* fd         = (const float*)d_in[3];
    const float* Wa         = (const float*)d_in[4];
    const float* Wb         = (const float*)d_in[5];
    const float* Wc         = (const float*)d_in[6];
    const float* Wd         = (const float*)d_in[7];
    const float* fuse_w     = (const float*)d_in[8];
    const float* fuse_b     = (const float*)d_in[9];
    const float* fuse_gamma = (const float*)d_in[10];
    const float* fuse_beta  = (const float*)d_in[11];
    const float* gamma_cam  = (const float*)d_in[12];
    const float* out_w      = (const float*)d_in[13];
    const float* out_b      = (const float*)d_in[14];
    const float* out_gamma  = (const float*)d_in[15];
    const float* out_beta   = (const float*)d_in[16];
    float* out = (float*)d_out;

    k_zero<<<288, 256>>>();
    k_gram<<<dim3(36, B), 256>>>(xa, fb, fc, fd);
    k_attn<<<dim3(4, B), 256>>>(Wa, Wb, Wc, Wd, fuse_w);
    k_fuse<<<dim3(NN/256, B), 256>>>(xa, fb, fc, fd, fuse_b);
    k_bnfin<<<1, 48>>>(fuse_gamma, fuse_beta, 0);
    k_pre<<<(B*C*NN)/1024, 256>>>(xa, gamma_cam);
    k_conv<<<dim3(WW/32, HH/8, B), 256>>>(out_w, out_b, out);
    k_bnfin<<<1, 48>>>(out_gamma, out_beta, 1);
    k_final<<<(B*C*NN)/1024, 256>>>(out);
}

// round 14
// speedup vs baseline: 1.8114x; 1.0555x over previous
#include <cuda_runtime.h>
#include <math.h>

#define B  8
#define C  48
#define HH 192
#define WW 192
#define NN (HH*WW)   // 36864

// ---------------- scratch (no allocations allowed) ----------------
__device__ float  g_G[4*B*C*C];        // Gram matrices  [s][b][c][d]
__device__ float  g_Pt[B*4*C*C];       // P transposed   [b][s][e][co]
__device__ float  g_y1[B*C*NN];        // fuse output; overwritten with t by k_pre
__device__ double g_stats[4*C];        // sum1, sq1, sum2, sq2
__device__ float  g_bn[4*C];           // scale1, shift1, scale2, shift2

__device__ __forceinline__ float dot48(const float* __restrict__ a, const float* __restrict__ b) {
    float s = 0.f;
    #pragma unroll
    for (int k = 0; k < 12; k++) {
        const float4 x = ((const float4*)a)[k];
        const float4 y = ((const float4*)b)[k];
        s += x.x*y.x + x.y*y.y + x.z*y.z + x.w*y.w;
    }
    return s;
}

// ---------------- tf32 helpers (verified in R7) ----------------
__device__ __forceinline__ void split_tf32(float x, unsigned& hi, unsigned& lo) {
    unsigned h;
    asm("cvt.rna.tf32.f32 %0, %1;" : "=r"(h) : "f"(x));
    float r = x - __uint_as_float(h);
    unsigned l;
    asm("cvt.rna.tf32.f32 %0, %1;" : "=r"(l) : "f"(r));
    hi = h; lo = l;
}
__device__ __forceinline__ void mma_tf32(float d[4], const unsigned a[4], const unsigned b[2]) {
    asm volatile(
        "mma.sync.aligned.m16n8k8.row.col.f32.tf32.tf32.f32 "
        "{%0,%1,%2,%3}, {%4,%5,%6,%7}, {%8,%9}, {%0,%1,%2,%3};"
        : "+f"(d[0]), "+f"(d[1]), "+f"(d[2]), "+f"(d[3])
        : "r"(a[0]), "r"(a[1]), "r"(a[2]), "r"(a[3]), "r"(b[0]), "r"(b[1]));
}

// ---------------- zero scratch ----------------
__global__ void k_zero() {
    int i = blockIdx.x * 256 + threadIdx.x;
    if (i < 4*B*C*C) g_G[i] = 0.f;
    if (i < 4*C)     g_stats[i] = 0.0;
}

// ---------------- pass A: Gram via tf32 mma.sync (3-term split) ----------------
// grid (16, B) = 128 blocks, 384 threads (12 warps). warp -> (gram s = w/3, N-tiles 2(w%3)+{0,1})
// smem: [s][c][k] rows, stride 52 (bank-complete). chunk = 2304 n = 48 tiles of 48.
__global__ __launch_bounds__(384) void k_gram(const float* __restrict__ xa,
                                              const float* __restrict__ xb,
                                              const float* __restrict__ xc,
                                              const float* __restrict__ xd) {
    __shared__ float sX[4*48*52];   // 39936 B
    const int b     = blockIdx.y;
    const int chunk = blockIdx.x;   // 16 chunks of 2304
    const int tid  = threadIdx.x;
    const int warp = tid >> 5, lane = tid & 31;
    const int g = lane >> 2, t = lane & 3;
    const int s   = warp / 3;          // gram id
    const int nt2 = (warp - s*3) * 2;  // N-tile base

    float acc[3][2][4];
    #pragma unroll
    for (int m = 0; m < 3; m++)
        #pragma unroll
        for (int j = 0; j < 2; j++)
            #pragma unroll
            for (int k = 0; k < 4; k++) acc[m][j][k] = 0.f;

    const size_t base = (size_t)b * C * NN + (size_t)chunk * 2304;
    const float* src[4] = {xa, xb, xc, xd};

    // staging: 4*48*48 = 9216 elems / 384 thr = 24 each; register prefetch
    float r[24];
    #pragma unroll
    for (int k = 0; k < 24; k++) {
        const int idx = tid + 384*k;
        const int s2 = idx / 2304, rem = idx - s2*2304;
        const int c = rem / 48, nl = rem - c*48;
        r[k] = src[s2][base + (size_t)c * NN + nl];    // tile 0
    }

    const float* A  = sX;                 // xa
    const float* Bm = sX + s*2496;        // xs   (48*52)

    for (int tile = 0; tile < 48; tile++) {
        __syncthreads();   // previous tile's consumers done
        #pragma unroll
        for (int k = 0; k < 24; k++) {
            const int idx = tid + 384*k;
            const int s2 = idx / 2304, rem = idx - s2*2304;
            const int c = rem / 48, nl = rem - c*48;
            sX[(s2*48 + c)*52 + nl] = r[k];
        }
        __syncthreads();   // smem ready
        if (tile < 47) {
            const int n0 = (tile + 1) * 48;
            #pragma unroll
            for (int k = 0; k < 24; k++) {
                const int idx = tid + 384*k;
                const int s2 = idx / 2304, rem = idx - s2*2304;
                const int c = rem / 48, nl = rem - c*48;
                r[k] = src[s2][base + (size_t)c * NN + n0 + nl];
            }
        }
        for (int k8 = 0; k8 < 6; k8++) {
            const int k0 = k8 * 8;
            unsigned ahi[3][4], alo[3][4];
            #pragma unroll
            for (int m = 0; m < 3; m++) {
                split_tf32(A[(16*m + g    )*52 + k0 + t    ], ahi[m][0], alo[m][0]);
                split_tf32(A[(16*m + g + 8)*52 + k0 + t    ], ahi[m][1], alo[m][1]);
                split_tf32(A[(16*m + g    )*52 + k0 + t + 4], ahi[m][2], alo[m][2]);
                split_tf32(A[(16*m + g + 8)*52 + k0 + t + 4], ahi[m][3], alo[m][3]);
            }
            unsigned bhi[2][2], blo[2][2];
            #pragma unroll
            for (int j = 0; j < 2; j++) {
                const int dr = 8*(nt2 + j) + g;
                split_tf32(Bm[dr*52 + k0 + t    ], bhi[j][0], blo[j][0]);
                split_tf32(Bm[dr*52 + k0 + t + 4], bhi[j][1], blo[j][1]);
            }
            #pragma unroll
            for (int m = 0; m < 3; m++)
                #pragma unroll
                for (int j = 0; j < 2; j++) {
                    mma_tf32(acc[m][j], alo[m], bhi[j]);
                    mma_tf32(acc[m][j], ahi[m], blo[j]);
                    mma_tf32(acc[m][j], ahi[m], bhi[j]);
                }
        }
    }
    // epilogue: D frag rows c = 16m+g (+8), cols d = 8(nt2+j)+2t (+1)
    #pragma unroll
    for (int m = 0; m < 3; m++)
        #pragma unroll
        for (int j = 0; j < 2; j++) {
            const int c0 = 16*m + g;
            const int d0 = 8*(nt2 + j) + 2*t;
            float* Gp = &g_G[((size_t)(s*B + b)*48)*48];
            atomicAdd(&Gp[ c0     *48 + d0    ], acc[m][j][0]);
            atomicAdd(&Gp[ c0     *48 + d0 + 1], acc[m][j][1]);
            atomicAdd(&Gp[(c0 + 8)*48 + d0    ], acc[m][j][2]);
            atomicAdd(&Gp[(c0 + 8)*48 + d0 + 1], acc[m][j][3]);
        }
}

// ---------------- pass B: energy -> attention -> M -> P — float4 inner-product version ----------------
__global__ __launch_bounds__(256) void k_attn(const float* __restrict__ Wa,
                                              const float* __restrict__ Wb,
                                              const float* __restrict__ Wc,
                                              const float* __restrict__ Wd,
                                              const float* __restrict__ fuse_w) {
    __shared__ float sA[48*52];
    __shared__ float sB[48*52];
    __shared__ float sC[48*52];
    __shared__ float sD[48*52];
    const int s = blockIdx.x, b = blockIdx.y, tid = threadIdx.x;
    const float* Wsp = (s == 0) ? Wa : (s == 1) ? Wb : (s == 2) ? Wc : Wd;

    for (int i = tid; i < 2304; i += 256) {
        const int r = i / 48, q = i - r*48;
        sA[r*52+q] = g_G[(s*B + b)*2304 + i];
        sB[r*52+q] = Wa[i];
        sC[r*52+q] = Wsp[i];
    }
    __syncthreads();
    for (int i = tid; i < 2304; i += 256) {
        const int e = i / 48, d = i - e*48;
        sD[d*52+e] = dot48(&sA[e*52], &sC[d*52]);
    }
    __syncthreads();
    for (int i = tid; i < 2304; i += 256) {
        const int c = i / 48, d = i - c*48;
        sA[c*52+d] = dot48(&sB[c*52], &sD[d*52]);
    }
    __syncthreads();
    if (tid < 48) {
        const int c = tid;
        float mn = sA[c*52];
        for (int d = 1; d < 48; d++) mn = fminf(mn, sA[c*52+d]);
        float sum = 0.f;
        for (int d = 0; d < 48; d++) { const float v = expf(mn - sA[c*52+d]); sD[d*52+c] = v; sum += v; }
        const float inv = 1.f / sum;
        for (int d = 0; d < 48; d++) sD[d*52+c] *= inv;
    }
    for (int i = tid; i < 2304; i += 256) {
        const int co = i / 48, c = i - co*48;
        sB[co*52+c] = fuse_w[co*192 + s*48 + c];
    }
    __syncthreads();
    for (int i = tid; i < 2304; i += 256) {
        const int co = i / 48, d = i - co*48;
        sA[co*52+d] = dot48(&sB[co*52], &sD[d*52]);
    }
    __syncthreads();
    for (int i = tid; i < 2304; i += 256) {
        const int d = i / 48, e = i - d*48;
        sB[e*52+d] = sC[d*52+e];
    }
    __syncthreads();
    for (int i = tid; i < 2304; i += 256) {
        const int co = i / 48, e = i - co*48;
        g_Pt[(((size_t)b*4 + s)*48 + e)*48 + co] = dot48(&sA[co*52], &sB[e*52]);
    }
}

// ---------------- pass C: fused 1x1 conv with register double-buffered staging ----------------
__global__ __launch_bounds__(256) void k_fuse(const float* __restrict__ xa,
                                              const float* __restrict__ xb,
                                              const float* __restrict__ xc,
                                              const float* __restrict__ xd,
                                              const float* __restrict__ fuse_b) {
    __shared__ float sW[48][48];
    __shared__ float sX[24][256];
    __shared__ float sstats[96];
    const int b  = blockIdx.y;
    const int n0 = blockIdx.x * 256;
    const int tid = threadIdx.x, tx = tid & 31, ty = tid >> 5;

    if (tid < 96) sstats[tid] = 0.f;

    float acc[6][8];
    #pragma unroll
    for (int i = 0; i < 6; i++)
        #pragma unroll
        for (int j = 0; j < 8; j++) acc[i][j] = 0.f;

    const float* src[4] = {xa, xb, xc, xd};
    const size_t xbase = (size_t)b*48*NN + n0 + tid;
    const float* ptb = &g_Pt[(size_t)b*4*2304];

    float xr[24];
    #pragma unroll
    for (int k = 0; k < 24; k++) xr[k] = src[0][xbase + (size_t)k*NN];
    float wr[9];
    #pragma unroll
    for (int j = 0; j < 9; j++) wr[j] = ptb[tid + 256*j];

    for (int step = 0; step < 8; step++) {
        const int ch = step & 1, e0 = ch * 24;
        __syncthreads();
        if (ch == 0) {
            #pragma unroll
            for (int j = 0; j < 9; j++) sW[0][tid + 256*j] = wr[j];
        }
        #pragma unroll
        for (int k = 0; k < 24; k++) sX[k][tid] = xr[k];
        __syncthreads();
        if (step < 7) {
            const int ns = (step + 1) >> 1, nch = (step + 1) & 1, ne0 = nch * 24;
            const float* nf = src[ns];
            #pragma unroll
            for (int k = 0; k < 24; k++) xr[k] = nf[xbase + (size_t)(ne0 + k)*NN];
            if (nch == 0) {
                #pragma unroll
                for (int j = 0; j < 9; j++) wr[j] = ptb[ns*2304 + tid + 256*j];
            }
        }
        #pragma unroll 2
        for (int el = 0; el < 24; el++) {
            const float4 x0 = *(const float4*)&sX[el][4*tx];
            const float4 x1 = *(const float4*)&sX[el][4*tx + 128];
            #pragma unroll
            for (int i = 0; i < 6; i++) {
                const float wv = sW[e0 + el][ty + 8*i];
                acc[i][0] += wv*x0.x; acc[i][1] += wv*x0.y;
                acc[i][2] += wv*x0.z; acc[i][3] += wv*x0.w;
                acc[i][4] += wv*x1.x; acc[i][5] += wv*x1.y;
                acc[i][6] += wv*x1.z; acc[i][7] += wv*x1.w;
            }
        }
    }
    __syncthreads();

    #pragma unroll
    for (int i = 0; i < 6; i++) {
        const int co = ty + 8*i;
        const float fb_ = fuse_b[co];
        float4 o0, o1;
        o0.x = acc[i][0]+fb_; o0.y = acc[i][1]+fb_; o0.z = acc[i][2]+fb_; o0.w = acc[i][3]+fb_;
        o1.x = acc[i][4]+fb_; o1.y = acc[i][5]+fb_; o1.z = acc[i][6]+fb_; o1.w = acc[i][7]+fb_;
        float* row = &g_y1[((size_t)b*48 + co)*NN + n0];
        *(float4*)&row[4*tx]       = o0;
        *(float4*)&row[4*tx + 128] = o1;
        float lsum = o0.x+o0.y+o0.z+o0.w + o1.x+o1.y+o1.z+o1.w;
        float lsq  = o0.x*o0.x+o0.y*o0.y+o0.z*o0.z+o0.w*o0.w
                   + o1.x*o1.x+o1.y*o1.y+o1.z*o1.z+o1.w*o1.w;
        for (int o = 16; o > 0; o >>= 1) {
            lsum += __shfl_down_sync(0xffffffffu, lsum, o);
            lsq  += __shfl_down_sync(0xffffffffu, lsq,  o);
        }
        if (tx == 0) { atomicAdd(&sstats[co], lsum); atomicAdd(&sstats[48+co], lsq); }
    }
    __syncthreads();
    if (tid < 48) {
        atomicAdd(&g_stats[tid],      (double)sstats[tid]);
        atomicAdd(&g_stats[48 + tid], (double)sstats[48 + tid]);
    }
}

// ---------------- BN finalize (tiny) ----------------
__global__ void k_bnfin(const float* __restrict__ gamma, const float* __restrict__ beta, int which) {
    const int c = threadIdx.x;
    if (c >= 48) return;
    const double cnt  = (double)B * NN;
    const double mean = g_stats[which*96 + c] / cnt;
    const double var  = g_stats[which*96 + 48 + c] / cnt - mean*mean;
    const float  sc   = (float)((double)gamma[c] / sqrt(var + 1e-5));
    const float  sh   = beta[c] - (float)mean * sc;
    g_bn[which*96 + c]      = sc;
    g_bn[which*96 + 48 + c] = sh;
}

// ---------------- pass D: t = gamma_cam*relu(bn1(y1)) + input, in place into g_y1 ----------------
__global__ void k_pre(const float* __restrict__ inp, const float* __restrict__ gamma_cam) {
    const size_t i = ((size_t)blockIdx.x * 256 + threadIdx.x) * 4;
    const int co = (int)((i / NN) % 48);
    const float sc = g_bn[co], sh = g_bn[48 + co];
    const float gcam = gamma_cam[0];
    float4 y = *(float4*)(g_y1 + i);
    const float4 x = *(const float4*)(inp + i);
    y.x = gcam * fmaxf(y.x*sc + sh, 0.f) + x.x;
    y.y = gcam * fmaxf(y.y*sc + sh, 0.f) + x.y;
    y.z = gcam * fmaxf(y.z*sc + sh, 0.f) + x.z;
    y.w = gcam * fmaxf(y.w*sc + sh, 0.f) + x.w;
    *(float4*)(g_y1 + i) = y;
}

// ---------------- pass E: 3x3 conv with register double-buffered staging (R11 proven) ----------------
__global__ __launch_bounds__(256) void k_conv(const float* __restrict__ out_w,
                                              const float* __restrict__ out_b,
                                              float* __restrict__ out) {
    __shared__ float sW[48*9];
    __shared__ float sT[10*34];
    __shared__ float ssum[48], ssq[48];
    const int b   = blockIdx.z;
    const int hy0 = blockIdx.y * 8;
    const int wx0 = blockIdx.x * 32;
    const int tid = threadIdx.x;
    const int cg  = tid >> 6;
    const int p   = tid & 63;
    const int px  = p & 31;
    const int py2 = p >> 5;

    if (tid < 48) { ssum[tid] = 0.f; ssq[tid] = 0.f; }

    const int r0 = tid / 34, c0 = tid - r0*34;
    const int gh0 = hy0 + r0 - 1, gw0 = wx0 + c0 - 1;
    const bool ok0 = (gh0 >= 0 && gh0 < HH && gw0 >= 0 && gw0 < WW) && (tid < 340);
    const int off0 = ok0 ? (gh0*WW + gw0) : 0;
    const int i1 = tid + 256;
    const int r1 = i1 / 34, c1 = i1 - r1*34;
    const int gh1 = hy0 + r1 - 1, gw1 = wx0 + c1 - 1;
    const bool ok1 = (i1 < 340) && (gh1 >= 0 && gh1 < HH && gw1 >= 0 && gw1 < WW);
    const int off1 = ok1 ? (gh1*WW + gw1) : 0;
    const bool st1 = (i1 < 340);
    const int wco0 = tid / 9, wk0 = tid - wco0*9;
    const int wbase0 = wco0*432 + wk0;
    const int wco1 = i1 / 9, wk1 = i1 - wco1*9;
    const int wbase1 = wco1*432 + wk1;
    const bool wok1 = (i1 < 432);

    const float* tbase = g_y1 + (size_t)b*48*NN;

    float t0 = ok0 ? tbase[off0] : 0.f;
    float t1 = ok1 ? tbase[off1] : 0.f;
    float w0 = out_w[wbase0];
    float w1 = wok1 ? out_w[wbase1] : 0.f;

    float acc[48];
    #pragma unroll
    for (int i = 0; i < 48; i++) acc[i] = 0.f;

    for (int ci = 0; ci < 48; ci++) {
        __syncthreads();
        if (tid < 340) sT[tid] = t0;
        if (st1)       sT[i1]  = t1;
        sW[tid] = w0;
        if (wok1) sW[i1] = w1;
        __syncthreads();
        if (ci < 47) {
            const float* tp = tbase + (size_t)(ci + 1)*NN;
            t0 = ok0 ? tp[off0] : 0.f;
            t1 = ok1 ? tp[off1] : 0.f;
            w0 = out_w[wbase0 + (ci + 1)*9];
            w1 = wok1 ? out_w[wbase1 + (ci + 1)*9] : 0.f;
        }

        float v[6][3];
        const int baseRow = py2 * 4;
        #pragma unroll
        for (int rr = 0; rr < 6; rr++)
            #pragma unroll
            for (int cc = 0; cc < 3; cc++)
                v[rr][cc] = sT[(baseRow + rr)*34 + px + cc];

        #pragma unroll
        for (int j = 0; j < 12; j++) {
            const float* wp = &sW[(cg*12 + j)*9];
            const float q0=wp[0],q1=wp[1],q2=wp[2],q3=wp[3],q4=wp[4],q5=wp[5],q6=wp[6],q7=wp[7],q8=wp[8];
            #pragma unroll
            for (int r = 0; r < 4; r++) {
                acc[j*4 + r] += q0*v[r  ][0] + q1*v[r  ][1] + q2*v[r  ][2]
                              + q3*v[r+1][0] + q4*v[r+1][1] + q5*v[r+1][2]
                              + q6*v[r+2][0] + q7*v[r+2][1] + q8*v[r+2][2];
            }
        }
    }

    #pragma unroll
    for (int j = 0; j < 12; j++) {
        const int co = cg*12 + j;
        const float bo = out_b[co];
        float lsum = 0.f, lsq = 0.f;
        #pragma unroll
        for (int r = 0; r < 4; r++) {
            const float val = acc[j*4 + r] + bo;
            const int gh = hy0 + py2*4 + r, gw = wx0 + px;
            out[((size_t)b*48 + co)*NN + gh*WW + gw] = val;
            lsum += val; lsq += val*val;
        }
        for (int o = 16; o > 0; o >>= 1) {
            lsum += __shfl_down_sync(0xffffffffu, lsum, o);
            lsq  += __shfl_down_sync(0xffffffffu, lsq,  o);
        }
        if ((tid & 31) == 0) { atomicAdd(&ssum[co], lsum); atomicAdd(&ssq[co], lsq); }
    }
    __syncthreads();
    if (tid < 48) {
        atomicAdd(&g_stats[96 + tid],  (double)ssum[tid]);
        atomicAdd(&g_stats[144 + tid], (double)ssq[tid]);
    }
}

// ---------------- pass G: in-place relu(bn2(y2)) ----------------
__global__ void k_final(float* __restrict__ out) {
    const size_t i = ((size_t)blockIdx.x * 256 + threadIdx.x) * 4;
    const int co = (int)((i / NN) % 48);
    const float sc = g_bn[96 + co], sh = g_bn[144 + co];
    float4 v = *(float4*)(out + i);
    v.x = fmaxf(v.x*sc + sh, 0.f);
    v.y = fmaxf(v.y*sc + sh, 0.f);
    v.z = fmaxf(v.z*sc + sh, 0.f);
    v.w = fmaxf(v.w*sc + sh, 0.f);
    *(float4*)(out + i) = v;
}

// ---------------- launch ----------------
extern "C" void kernel_launch(void* const* d_in, const int* in_sizes, int n_in,
                              void* d_out, int out_size) {
    const float* xa         = (const float*)d_in[0];
    const float* fb         = (const float*)d_in[1];
    const float* fc         = (const float*)d_in[2];
    const float* fd         = (const float*)d_in[3];
    const float* Wa         = (const float*)d_in[4];
    const float* Wb         = (const float*)d_in[5];
    const float* Wc         = (const float*)d_in[6];
    const float* Wd         = (const float*)d_in[7];
    const float* fuse_w     = (const float*)d_in[8];
    const float* fuse_b     = (const float*)d_in[9];
    const float* fuse_gamma = (const float*)d_in[10];
    const float* fuse_beta  = (const float*)d_in[11];
    const float* gamma_cam  = (const float*)d_in[12];
    const float* out_w      = (const float*)d_in[13];
    const float* out_b      = (const float*)d_in[14];
    const float* out_gamma  = (const float*)d_in[15];
    const float* out_beta   = (const float*)d_in[16];
    float* out = (float*)d_out;

    k_zero<<<288, 256>>>();
    k_gram<<<dim3(16, B), 384>>>(xa, fb, fc, fd);
    k_attn<<<dim3(4, B), 256>>>(Wa, Wb, Wc, Wd, fuse_w);
    k_fuse<<<dim3(NN/256, B), 256>>>(xa, fb, fc, fd, fuse_b);
    k_bnfin<<<1, 48>>>(fuse_gamma, fuse_beta, 0);
    k_pre<<<(B*C*NN)/1024, 256>>>(xa, gamma_cam);
    k_conv<<<dim3(WW/32, HH/8, B), 256>>>(out_w, out_b, out);
    k_bnfin<<<1, 48>>>(out_gamma, out_beta, 1);
    k_final<<<(B*C*NN)/1024, 256>>>(out);
}